// round 17
// baseline (speedup 1.0000x reference)
#include <cuda_runtime.h>
#include <cstdint>

// Chamfer distance: ONE persistent kernel, 512 co-resident CTAs, G=48
// (cs=0.2). R16: bulk phase scans ONLY the r=1 cube (4-lane groups, ~4 pts);
// the ~15% uncertified queries are enqueued and processed by a WARP-PER-QUERY
// expanding-ring phase (rows spread across 32 lanes, full-mask reductions are
// warp-uniform) — escalation becomes balanced warp tasks instead of
// intra-warp divergent serial work, and the 256KB brute sweeps are gone.
// Finisher-ticket finalize (no extra barrier).
// Determinism: per-query mins exact; sums fixed-point u64 (order-invariant).

#define NPTS   16384
#define G      48
#define NC     (G * G * G)                 // 110592
#define NCTA   512
#define NTHR   256
#define NTOT   (NCTA * NTHR)               // 131072 = 4 * 2 * NPTS
#define NWARP  (NTOT / 32)                 // 4096
#define BOXB   4.8f
#define CS     (2.0f * BOXB / (float)G)    // 0.2
#define INV_CS (1.0f / CS)
#define CS2    (CS * CS)                   // 0.04 r=1 certification bound

typedef unsigned long long u64;
typedef unsigned int u32;

// ---------- scratch (__device__ globals; zero-initialized at load) ----------
__device__ u32    g_pcnt[NC];              // packed counts c0|c1<<16 (re-zeroed)
__device__ int    g_starts[2][NC + 1];
__device__ int    g_cursor[2][NC];
__device__ u32    g_part[NCTA];            // packed CTA partial sums
__device__ float4 g_pre[2][NPTS];          // staged {-2x,-2y,-2z,|p|^2}
__device__ int    g_cellid[2][NPTS];
__device__ float4 g_sorted[2][NPTS];
__device__ int    g_fb[2 * NPTS];          // escalation queue: query ids
__device__ u32    g_fbmin[2 * NPTS];       // per-task results (one writer each)
__device__ int    g_fb_cnt;                // reset by finisher
__device__ int    g_fb_done;               // reset by finisher
__device__ u64    g_sum;                   // reset by finisher
__device__ int    g_bar_cnt;
__device__ int    g_bar_sense;

// ---------- device-wide barrier ----------
__device__ __forceinline__ int ld_acq(const int* p) {
    int v; asm volatile("ld.acquire.gpu.b32 %0, [%1];" : "=r"(v) : "l"(p)); return v;
}
__device__ __forceinline__ void st_rel(int* p, int v) {
    asm volatile("st.release.gpu.b32 [%0], %1;" :: "l"(p), "r"(v) : "memory");
}
__device__ __forceinline__ void grid_bar(int& sense) {
    __syncthreads();
    if (threadIdx.x == 0) {
        int target = sense ^ 1;
        __threadfence();
        int a = atomicAdd(&g_bar_cnt, 1);
        if (a == NCTA - 1) {
            atomicExch(&g_bar_cnt, 0);      // reset BEFORE release
            st_rel(&g_bar_sense, target);
        } else {
            while (ld_acq(&g_bar_sense) != target) __nanosleep(32);
        }
        __threadfence();
    }
    sense ^= 1;
    __syncthreads();
}

__device__ __forceinline__ int cell1(float v) {
    int c = (int)floorf((v + BOXB) * INV_CS);
    return c < 0 ? 0 : (c > G - 1 ? G - 1 : c);
}
__device__ __forceinline__ float pdist(float4 B, float qx, float qy, float qz) {
    return fmaf(qz, B.z, fmaf(qy, B.y, fmaf(qx, B.x, B.w)));
}
__device__ __forceinline__ void scan_range(const float4* __restrict__ tgt,
                                           int j, int e,
                                           float qx, float qy, float qz, float& m) {
    for (; j < e; j++) m = fminf(m, pdist(__ldg(&tgt[j]), qx, qy, qz));
}

__global__ __launch_bounds__(NTHR, 4)
void cd_fused_kernel(const float* __restrict__ gt, const float* __restrict__ gen,
                     float* __restrict__ out) {
    __shared__ u32 s_wsum[8];
    __shared__ u32 s_off;

    const int tid  = threadIdx.x;
    const int t    = blockIdx.x * NTHR + tid;       // 0 .. NTOT-1
    const int wid  = tid >> 5, lane = tid & 31;
    int sense = ld_acq(&g_bar_sense);

    // ---- P1: packed histogram + stage ----
    if (t < 2 * NPTS) {
        const int cloud = t >> 14, i = t & (NPTS - 1);
        const float* p = (cloud == 0 ? gt : gen) + 3 * i;
        float x = p[0], y = p[1], z = p[2];
        int cell = (cell1(z) * G + cell1(y)) * G + cell1(x);
        atomicAdd(&g_pcnt[cell], cloud == 0 ? 1u : 0x10000u);
        g_pre[cloud][i]    = make_float4(-2.0f * x, -2.0f * y, -2.0f * z,
                                         x * x + y * y + z * z);
        g_cellid[cloud][i] = cell;
    }
    grid_bar(sense);                                // GB1

    // ---- P2a: packed two-level warp scan, one cell per thread ----
    const int  cidx = t;
    const bool cact = (cidx < NC);
    const u32  cnt  = cact ? g_pcnt[cidx] : 0u;     // carry-free packed halves
    u32 incl = cnt;
#pragma unroll
    for (int s = 1; s < 32; s <<= 1) {
        u32 n = __shfl_up_sync(0xFFFFFFFFu, incl, s);
        if (lane >= s) incl += n;
    }
    if (lane == 31) s_wsum[wid] = incl;
    __syncthreads();
    if (wid == 0) {
        u32 w = (lane < 8) ? s_wsum[lane] : 0u;
#pragma unroll
        for (int s = 1; s < 8; s <<= 1) {
            u32 n = __shfl_up_sync(0xFFFFFFFFu, w, s);
            if (lane >= s) w += n;
        }
        if (lane < 8) s_wsum[lane] = w;
    }
    __syncthreads();
    const u32 wbase = (wid > 0) ? s_wsum[wid - 1] : 0u;
    const u32 excl  = wbase + incl - cnt;
    if (tid == NTHR - 1) g_part[blockIdx.x] = wbase + incl;
    grid_bar(sense);                                // GB2

    // ---- P2b: packed global offset, publish CSR, re-zero counts ----
    if (wid == 0) {
        u32 acc0 = 0u;
#pragma unroll
        for (int k = 0; k < NCTA / 32; k++) {
            int idx = k * 32 + lane;
            u32 pv = g_part[idx];
            if (idx < blockIdx.x) acc0 += pv;
        }
#pragma unroll
        for (int s = 16; s > 0; s >>= 1)
            acc0 += __shfl_xor_sync(0xFFFFFFFFu, acc0, s);
        if (lane == 0) s_off = acc0;
    }
    __syncthreads();
    if (cact) {
        u32 pk = s_off + excl;
        int s0 = (int)(pk & 0xFFFFu), s1 = (int)(pk >> 16);
        g_starts[0][cidx] = s0;  g_cursor[0][cidx] = s0;
        g_starts[1][cidx] = s1;  g_cursor[1][cidx] = s1;
        g_pcnt[cidx] = 0u;                          // re-zero for next replay
    }
    if (t == 0) { g_starts[0][NC] = NPTS; g_starts[1][NC] = NPTS; }
    grid_bar(sense);                                // GB3

    // ---- P3: scatter ----
    if (t < 2 * NPTS) {
        const int cloud = t >> 14, i = t & (NPTS - 1);
        int cell = g_cellid[cloud][i];
        int pos  = atomicAdd(&g_cursor[cloud][cell], 1);
        g_sorted[cloud][pos] = g_pre[cloud][i];
    }
    grid_bar(sense);                                // GB4

    // ---- P4a: 4-lane query, r=1 cube ONLY; uncertified -> queue ----
    const unsigned gmask = 0xFu << (lane & ~3);
    u64 acc = 0ull;
    {
        const int lane4 = t & 3;
        const int qi    = t >> 2;                   // 0 .. 2*NPTS-1
        const int dir   = qi >> 14;
        const int i     = qi & (NPTS - 1);
        const float4* __restrict__ tgt = g_sorted[dir ^ 1];
        const int*    __restrict__ st  = g_starts[dir ^ 1];

        float4 A = g_sorted[dir][i];
        float qx = -0.5f * A.x, qy = -0.5f * A.y, qz = -0.5f * A.z;
        float an = A.w;
        int cx = cell1(qx), cy = cell1(qy), cz = cell1(qz);

        float m = 3.4e38f;
        {   // r=1 cube: 9 rows over 4 lanes, this lane's <=3 rows interleaved
            int x0 = max(cx - 1, 0), x1 = min(cx + 1, G - 1);
            int j0 = 0, e0 = 0, j1 = 0, e1 = 0, j2 = 0, e2 = 0;
#pragma unroll
            for (int k0 = 0; k0 < 3; k0++) {
                int k = lane4 + k0 * 4;
                if (k < 9) {
                    int z = cz + k / 3 - 1, y = cy + k % 3 - 1;
                    if ((unsigned)z < G && (unsigned)y < G) {
                        int rb = (z * G + y) * G;
                        int js = __ldg(&st[rb + x0]);
                        int es = __ldg(&st[rb + x1 + 1]);
                        if (k0 == 0) { j0 = js; e0 = es; }
                        else if (k0 == 1) { j1 = js; e1 = es; }
                        else { j2 = js; e2 = es; }
                    }
                }
            }
            while ((j0 < e0) | (j1 < e1) | (j2 < e2)) {
                float4 B0, B1, B2;
                bool a0 = j0 < e0, a1 = j1 < e1, a2 = j2 < e2;
                if (a0) B0 = __ldg(&tgt[j0]);
                if (a1) B1 = __ldg(&tgt[j1]);
                if (a2) B2 = __ldg(&tgt[j2]);
                if (a0) { m = fminf(m, pdist(B0, qx, qy, qz)); j0++; }
                if (a1) { m = fminf(m, pdist(B1, qx, qy, qz)); j1++; }
                if (a2) { m = fminf(m, pdist(B2, qx, qy, qz)); j2++; }
            }
        }
        m = fminf(m, __shfl_xor_sync(gmask, m, 1));
        m = fminf(m, __shfl_xor_sync(gmask, m, 2));

        float d = fmaxf(m + an, 0.0f);
        if (d <= CS2) {                             // certified at r=1
            if (lane4 == 0) acc = (u64)((double)d * 4294967296.0);
        } else if (lane4 == 0) {                    // escalate to warp phase
            int slot = atomicAdd(&g_fb_cnt, 1);
            g_fb[slot] = qi;
        }
    }
    __syncwarp();
#pragma unroll
    for (int s = 16; s > 0; s >>= 1)
        acc += __shfl_down_sync(0xFFFFFFFFu, acc, s);
    if (lane == 0 && acc) atomicAdd(&g_sum, acc);
    grid_bar(sense);                                // GB5 (last barrier)

    // ---- P4b: WARP-PER-QUERY expanding-ring search; last task finalizes ----
    const int nf = *((volatile int*)&g_fb_cnt);
    if (nf > 0) {
        const int gwid = t >> 5;
        for (int task = gwid; task < nf; task += NWARP) {
            const int qi  = g_fb[task];
            const int dir = qi >> 14, i = qi & (NPTS - 1);
            float4 A = __ldg(&g_sorted[dir][i]);
            float qx = -0.5f * A.x, qy = -0.5f * A.y, qz = -0.5f * A.z;
            float an = A.w;
            const float4* __restrict__ tgt = g_sorted[dir ^ 1];
            const int*    __restrict__ st  = g_starts[dir ^ 1];
            const int cx = cell1(qx), cy = cell1(qy), cz = cell1(qz);

            float m = 3.4e38f;
            {   // r=1 cube: 9 rows across lanes (redo, tiny)
                int x0 = max(cx - 1, 0), x1 = min(cx + 1, G - 1);
                if (lane < 9) {
                    int z = cz + lane / 3 - 1, y = cy + lane % 3 - 1;
                    if ((unsigned)z < G && (unsigned)y < G) {
                        int rb = (z * G + y) * G;
                        scan_range(tgt, st[rb + x0], st[rb + x1 + 1], qx, qy, qz, m);
                    }
                }
            }
#pragma unroll
            for (int s = 16; s > 0; s >>= 1)
                m = fminf(m, __shfl_xor_sync(0xFFFFFFFFu, m, s));

            int r = 1;
            while (r < G) {                         // warp-uniform expansion
                float bound = (float)r * CS;
                if (m + an <= bound * bound) break;
                r++;
                const int side = 2 * r + 1, nrows = side * side;
                const int x0 = max(cx - r, 0), x1 = min(cx + r, G - 1);
                for (int k = lane; k < nrows; k += 32) {
                    int dz = k / side - r, dy = k % side - r;
                    int z = cz + dz, y = cy + dy;
                    if ((unsigned)z >= G || (unsigned)y >= G) continue;
                    int rb = (z * G + y) * G;
                    if (max(abs(dz), abs(dy)) == r) {
                        scan_range(tgt, st[rb + x0], st[rb + x1 + 1], qx, qy, qz, m);
                    } else {
                        if (cx - r >= 0)
                            scan_range(tgt, st[rb + cx - r], st[rb + cx - r + 1], qx, qy, qz, m);
                        if (cx + r <= G - 1)
                            scan_range(tgt, st[rb + cx + r], st[rb + cx + r + 1], qx, qy, qz, m);
                    }
                }
#pragma unroll
                for (int s = 16; s > 0; s >>= 1)
                    m = fminf(m, __shfl_xor_sync(0xFFFFFFFFu, m, s));
            }

            int ticket = 0;
            if (lane == 0) {
                *((volatile u32*)&g_fbmin[task]) =
                    __float_as_uint(fmaxf(m + an, 0.0f)); // single writer
                __threadfence();
                ticket = atomicAdd(&g_fb_done, 1) + 1;
            }
            ticket = __shfl_sync(0xFFFFFFFFu, ticket, 0);
            if (ticket == nf) {                     // last-completing task
                __threadfence();
                u64 a2 = 0ull;
                for (int f2 = lane; f2 < nf; f2 += 32)
                    a2 += (u64)((double)__uint_as_float(
                              *((volatile u32*)&g_fbmin[f2])) * 4294967296.0);
#pragma unroll
                for (int s = 16; s > 0; s >>= 1)
                    a2 += __shfl_down_sync(0xFFFFFFFFu, a2, s);
                if (lane == 0) {
                    u64 tot = atomicAdd(&g_sum, a2) + a2;
                    double sd = (double)tot * (1.0 / 4294967296.0);
                    out[0] = (float)(sd / (double)NPTS);  // mean1 + mean2
                    g_sum = 0ull; g_fb_cnt = 0; g_fb_done = 0;
                    __threadfence();
                }
            }
        }
    } else if (t == 0) {                            // no escalations
        u64 tot = atomicAdd(&g_sum, 0ull);
        double sd = (double)tot * (1.0 / 4294967296.0);
        out[0] = (float)(sd / (double)NPTS);
        g_sum = 0ull; g_fb_cnt = 0; g_fb_done = 0;
        __threadfence();
    }
}

extern "C" void kernel_launch(void* const* d_in, const int* in_sizes, int n_in,
                              void* d_out, int out_size) {
    const float* gt  = (const float*)d_in[0];
    const float* gen = (const float*)d_in[1];
    float* out = (float*)d_out;
    cd_fused_kernel<<<NCTA, NTHR>>>(gt, gen, out);
}